// round 6
// baseline (speedup 1.0000x reference)
#include <cuda_runtime.h>
#include <cstdint>

#define MM   128   // padded image side
#define NP   64    // patch side
#define NC   4     // channels / positions
#define C0   32    // (M - N) / 2
#define RB   16    // rows per thread (contiguous band)

#define STAGE_FLOATS (NP * NP * NC)          // 16384 floats = 64KB staging
#define SMEM_BYTES   ((STAGE_FLOATS + 8) * 4)

__device__ __forceinline__ uint32_t smem_u32(const void* p) {
    uint32_t a;
    asm("{ .reg .u64 t; cvta.to.shared.u64 t, %1; cvt.u32.u64 %0, t; }"
        : "=r"(a) : "l"(p));
    return a;
}

// block (2, 64, 4): tx = channel pair, ty = output column, tz = row band.
// Compute into SMEM staging, then one elected thread TMA-bulk-stores the
// CTA's contiguous 64KB output block (4 x 16KB UBLKCP) -> the 128MB output
// stream never touches the L1/LSU store path.
__global__ __launch_bounds__(512, 2)
void extract_patches_kernel(const float* __restrict__ img,
                            const float* __restrict__ pos,
                            float* __restrict__ out)
{
    extern __shared__ float smem[];
    float* stage = smem;                  // [16384] output staging
    float* spos  = smem + STAGE_FLOATS;   // [8] position scalars

    const int b = blockIdx.x;
    const float* I = img + (size_t)b * (MM * MM);

    const int lid = threadIdx.x + 2 * threadIdx.y + 128 * threadIdx.z;
    if (lid < 2 * NC)
        spos[lid] = pos[(size_t)b * (2 * NC) + lid];
    __syncthreads();

    const int col = threadIdx.y;          // output column j in [0, 64)
    const int i0  = threadIdx.z * RB;     // first row of this thread's band
    const int cb  = threadIdx.x * 2;      // first of this thread's 2 channels

    // Per-channel setup (2 channels): exact reference floor arithmetic.
    float wx[2], hprev[2], yif[2], oyv[2];
    int   off[2];
#pragma unroll
    for (int u = 0; u < 2; u++) {
        float ox = spos[cb + u];
        oyv[u]   = spos[NC + cb + u];

        float xx = (float)(col + C0) + ox;
        float x0 = floorf(xx);
        wx[u]    = xx - x0;
        int xi   = (int)x0;

        float yy = (float)(i0 + C0) + oyv[u];
        float y0 = floorf(yy);
        yif[u]   = y0;
        int yi   = (int)y0;

        // SHIFT_MAX=20, c0=32: yi,xi in [12,51]; deepest access stays < 128
        // -> the reference valid-mask is always true, no bounds checks.
        off[u] = yi * MM + xi;
        float a0 = __ldg(I + off[u]);
        float a1 = __ldg(I + off[u] + 1);
        hprev[u] = fmaf(a1 - a0, wx[u], a0);   // H(top row)
    }

    // Walk RB contiguous rows; each step loads only the new BOTTOM row taps
    // (2 per channel), reuses hprev, and stages the result in SMEM.
    float* sb = stage + ((size_t)i0 * NP + col) * NC + cb;
#pragma unroll
    for (int k = 0; k < RB; k++) {
        float2 res;
#pragma unroll
        for (int u = 0; u < 2; u++) {
            off[u] += MM;
            float b0 = __ldg(I + off[u]);
            float b1 = __ldg(I + off[u] + 1);
            float hnew = fmaf(b1 - b0, wx[u], b0);      // H(bottom row)

            float yy = (float)(i0 + k + C0) + oyv[u];
            float wy = yy - (yif[u] + (float)k);

            float r  = fmaf(hnew - hprev[u], wy, hprev[u]);
            hprev[u] = hnew;
            if (u == 0) res.x = r; else res.y = r;
        }
        // Conflict-free STS.64: warp writes one contiguous 256B run.
        *reinterpret_cast<float2*>(sb + (size_t)k * (NP * NC)) = res;
    }
    __syncthreads();

    // One thread bulk-stores the CTA's 64KB contiguous output block.
    if (lid == 0) {
        asm volatile("fence.proxy.async.shared::cta;" ::: "memory");
        const float* gdst = out + (size_t)b * STAGE_FLOATS;
        uint32_t ssrc = smem_u32(stage);
#pragma unroll
        for (int q = 0; q < 4; q++) {
            asm volatile(
                "cp.async.bulk.global.shared::cta.bulk_group [%0], [%1], %2;"
                :: "l"(gdst + q * (STAGE_FLOATS / 4)),
                   "r"(ssrc + q * (STAGE_FLOATS / 4) * 4),
                   "n"((STAGE_FLOATS / 4) * 4)
                : "memory");
        }
        asm volatile("cp.async.bulk.commit_group;" ::: "memory");
        asm volatile("cp.async.bulk.wait_group 0;" ::: "memory");
    }
}

extern "C" void kernel_launch(void* const* d_in, const int* in_sizes, int n_in,
                              void* d_out, int out_size)
{
    const float* img = (const float*)d_in[0];   // padded_obj (B,128,128,1)
    const float* pos = (const float*)d_in[1];   // positions  (B,1,2,4)
    float* out = (float*)d_out;                 // (B,64,64,4)

    int B = in_sizes[0] / (MM * MM);

    cudaFuncSetAttribute(extract_patches_kernel,
                         cudaFuncAttributeMaxDynamicSharedMemorySize,
                         SMEM_BYTES);

    dim3 block(2, 64, 4);
    extract_patches_kernel<<<B, block, SMEM_BYTES>>>(img, pos, out);
}

// round 7
// speedup vs baseline: 1.3353x; 1.3353x over previous
#include <cuda_runtime.h>

#define MM   128   // padded image side
#define NP   64    // patch side
#define NC   4     // channels / positions
#define C0   32    // (M - N) / 2
#define RB   32    // rows per thread (contiguous band)

// block (2, 64, 2): tx = channel pair (fastest -> warp float2 stores form one
// contiguous 256B full-sector run), ty = output column, tz = row band.
// 256 threads/CTA, 6 CTAs/SM target. Depth-1 software prefetch of the next
// row's taps hides L1/L2 load latency behind the current row's FMA chain.
__global__ __launch_bounds__(256, 6)
void extract_patches_kernel(const float* __restrict__ img,
                            const float* __restrict__ pos,
                            float* __restrict__ out)
{
    const int b = blockIdx.x;
    const float* I = img + (size_t)b * (MM * MM);

    // Stage the 8 position scalars: layout (B,1,2,C); dim0 = ox, dim1 = oy.
    __shared__ float spos[2 * NC];
    const int lid = threadIdx.x + 2 * threadIdx.y + 128 * threadIdx.z;
    if (lid < 2 * NC)
        spos[lid] = pos[(size_t)b * (2 * NC) + lid];
    __syncthreads();

    const int col = threadIdx.y;          // output column j in [0, 64)
    const int i0  = threadIdx.z * RB;     // first row of this thread's band
    const int cb  = threadIdx.x * 2;      // first of this thread's 2 channels

    // Per-channel setup. wy is hoisted to a band constant: yy advances by
    // exactly 1.0 per row, so frac(yy) is constant to <=2 ulp; bilinear is
    // continuous in yy, so output error is ~1e-5 << 1e-3 tolerance.
    float wx[2], wy[2], hprev[2];
    const float* base[2];
#pragma unroll
    for (int u = 0; u < 2; u++) {
        float ox = spos[cb + u];
        float oy = spos[NC + cb + u];

        float xx = (float)(col + C0) + ox;
        float x0 = floorf(xx);
        wx[u]    = xx - x0;
        int xi   = (int)x0;

        float yy = (float)(i0 + C0) + oy;
        float y0 = floorf(yy);
        wy[u]    = yy - y0;
        int yi   = (int)y0;

        // SHIFT_MAX=20, c0=32: yi,xi in [12,51]; deepest access yi+RB rows,
        // xi+1 cols stays < 128 -> the reference valid-mask is always true.
        base[u] = I + yi * MM + xi;
        float a0 = __ldg(base[u]);
        float a1 = __ldg(base[u] + 1);
        hprev[u] = fmaf(a1 - a0, wx[u], a0);   // H(top row)
    }

    // Prefetch row 0's bottom taps.
    float nb0[2], nb1[2];
#pragma unroll
    for (int u = 0; u < 2; u++) {
        nb0[u] = __ldg(base[u] + MM);
        nb1[u] = __ldg(base[u] + MM + 1);
    }

    // Output: (B, 64, 64, 4); channels cb..cb+1 at column `col`,
    // rows i0..i0+RB-1. Warp-contiguous full-sector float2 stores.
    float* ob = out + ((size_t)b * (NP * NP) + (size_t)i0 * NP + col) * NC + cb;

#pragma unroll
    for (int k = 0; k < RB; k++) {
        // Consume this row's prefetched taps.
        float c00 = nb0[0], c01 = nb1[0];
        float c10 = nb0[1], c11 = nb1[1];

        // Issue next row's 4 independent loads before the FMA chain.
        if (k + 1 < RB) {
            nb0[0] = __ldg(base[0] + (k + 2) * MM);
            nb1[0] = __ldg(base[0] + (k + 2) * MM + 1);
            nb0[1] = __ldg(base[1] + (k + 2) * MM);
            nb1[1] = __ldg(base[1] + (k + 2) * MM + 1);
        }

        float2 res;
        {
            float hnew = fmaf(c01 - c00, wx[0], c00);
            res.x      = fmaf(hnew - hprev[0], wy[0], hprev[0]);
            hprev[0]   = hnew;
        }
        {
            float hnew = fmaf(c11 - c10, wx[1], c10);
            res.y      = fmaf(hnew - hprev[1], wy[1], hprev[1]);
            hprev[1]   = hnew;
        }
        // Streaming store: output never re-read; full-sector coverage.
        __stcs(reinterpret_cast<float2*>(ob + (size_t)k * (NP * NC)), res);
    }
}

extern "C" void kernel_launch(void* const* d_in, const int* in_sizes, int n_in,
                              void* d_out, int out_size)
{
    const float* img = (const float*)d_in[0];   // padded_obj (B,128,128,1)
    const float* pos = (const float*)d_in[1];   // positions  (B,1,2,4)
    float* out = (float*)d_out;                 // (B,64,64,4)

    int B = in_sizes[0] / (MM * MM);
    dim3 block(2, 64, 2);
    extract_patches_kernel<<<B, block>>>(img, pos, out);
}

// round 8
// speedup vs baseline: 1.3617x; 1.0198x over previous
#include <cuda_runtime.h>

#define MM   128   // padded image side
#define NP   64    // patch side
#define NC   4     // channels / positions
#define C0   32    // (M - N) / 2
#define RB   8     // rows per thread (contiguous band)
#define BANDS_PER_IMG 4   // 4 CTAs per image, 16 rows each (2 z-bands of 8)

// block (2, 64, 2): tx = channel pair (fastest -> warp float2 stores form one
// contiguous 256B full-sector run), ty = output column, tz = sub-band.
// grid = B * 4: fine-grained CTAs (T_CTA/4) to kill wave-quantization tail
// (2.31 waves -> 9.2 waves) and cross-CTA spread.
__global__ __launch_bounds__(256, 6)
void extract_patches_kernel(const float* __restrict__ img,
                            const float* __restrict__ pos,
                            float* __restrict__ out)
{
    const int b    = blockIdx.x >> 2;          // image index
    const int band = blockIdx.x & 3;           // 16-row band within the patch
    const float* I = img + (size_t)b * (MM * MM);

    // Stage the 8 position scalars: layout (B,1,2,C); dim0 = ox, dim1 = oy.
    __shared__ float spos[2 * NC];
    const int lid = threadIdx.x + 2 * threadIdx.y + 128 * threadIdx.z;
    if (lid < 2 * NC)
        spos[lid] = pos[(size_t)b * (2 * NC) + lid];
    __syncthreads();

    const int col = threadIdx.y;                      // output column
    const int i0  = band * 16 + threadIdx.z * RB;     // first row of band
    const int cb  = threadIdx.x * 2;                  // first owned channel

    // Per-channel setup. wy hoisted to a band constant: yy advances by exactly
    // 1.0 per row, so frac(yy) is constant to <=2 ulp; bilinear is continuous
    // in yy -> output error ~1e-5 << 1e-3 tolerance (validated in R7).
    float wx[2], wy[2], hprev[2];
    const float* base[2];
#pragma unroll
    for (int u = 0; u < 2; u++) {
        float ox = spos[cb + u];
        float oy = spos[NC + cb + u];

        float xx = (float)(col + C0) + ox;
        float x0 = floorf(xx);
        wx[u]    = xx - x0;
        int xi   = (int)x0;

        float yy = (float)(i0 + C0) + oy;
        float y0 = floorf(yy);
        wy[u]    = yy - y0;
        int yi   = (int)y0;

        // SHIFT_MAX=20, c0=32: xi in [12,51], yi <= 108; deepest access
        // yi + RB + 1 <= 117 < 128 -> reference valid-mask is always true.
        base[u] = I + yi * MM + xi;
        float a0 = __ldg(base[u]);
        float a1 = __ldg(base[u] + 1);
        hprev[u] = fmaf(a1 - a0, wx[u], a0);   // H(top row)
    }

    // Prefetch row 0's bottom taps.
    float nb0[2], nb1[2];
#pragma unroll
    for (int u = 0; u < 2; u++) {
        nb0[u] = __ldg(base[u] + MM);
        nb1[u] = __ldg(base[u] + MM + 1);
    }

    // Output: (B, 64, 64, 4); channels cb..cb+1 at column `col`,
    // rows i0..i0+RB-1. Warp-contiguous full-sector float2 stores.
    float* ob = out + ((size_t)b * (NP * NP) + (size_t)i0 * NP + col) * NC + cb;

#pragma unroll
    for (int k = 0; k < RB; k++) {
        // Consume this row's prefetched taps.
        float c00 = nb0[0], c01 = nb1[0];
        float c10 = nb0[1], c11 = nb1[1];

        // Issue next row's 4 independent loads before the FMA chain.
        if (k + 1 < RB) {
            nb0[0] = __ldg(base[0] + (k + 2) * MM);
            nb1[0] = __ldg(base[0] + (k + 2) * MM + 1);
            nb0[1] = __ldg(base[1] + (k + 2) * MM);
            nb1[1] = __ldg(base[1] + (k + 2) * MM + 1);
        }

        float2 res;
        {
            float hnew = fmaf(c01 - c00, wx[0], c00);
            res.x      = fmaf(hnew - hprev[0], wy[0], hprev[0]);
            hprev[0]   = hnew;
        }
        {
            float hnew = fmaf(c11 - c10, wx[1], c10);
            res.y      = fmaf(hnew - hprev[1], wy[1], hprev[1]);
            hprev[1]   = hnew;
        }
        // Streaming store: output never re-read; full-sector coverage.
        __stcs(reinterpret_cast<float2*>(ob + (size_t)k * (NP * NC)), res);
    }
}

extern "C" void kernel_launch(void* const* d_in, const int* in_sizes, int n_in,
                              void* d_out, int out_size)
{
    const float* img = (const float*)d_in[0];   // padded_obj (B,128,128,1)
    const float* pos = (const float*)d_in[1];   // positions  (B,1,2,4)
    float* out = (float*)d_out;                 // (B,64,64,4)

    int B = in_sizes[0] / (MM * MM);
    dim3 block(2, 64, 2);
    extract_patches_kernel<<<B * BANDS_PER_IMG, block>>>(img, pos, out);
}